// round 14
// baseline (speedup 1.0000x reference)
#include <cuda_runtime.h>
#include <cstdint>

// Problem shape (fixed for this dataset):
//   pool: f32  [16, 128, 128, 64]  -> 16,777,216 elements
//   ind : i32  same shape, values in [0, 4,194,304)
//   out : f32  [16, 256, 256, 64]  -> 67,108,864 elements (256 MB)
// Per-batch flat scatter-ADD (duplicates sum).
//
// Final model (R3-R13, seven structural variants + RED/ATOM check):
//  - Wall = divergent-atomic service: ~2.1 cyc/atomic/SM, equivalently
//    ~64 B LTS sector-RMW per atomic -> 1.45 GB total LTS traffic ~= 129 us
//    chip floor. Measured scatter = 133.6 us (invariant to ILP, occupancy,
//    persistence, fusion, TMA, graph forks, RED vs atomicAdd).
//  - Kernel-issued zero stores consume the same LTS bandwidth (overlap is
//    conserved); driver cudaMemsetAsync zero-fill is nearly free (~11 us
//    for 256 MB) -> serialized memset-per-chunk is optimal.
//  - Output chunk must stay L2-resident during its scatter (4 x 64 MB
//    chunks; eviction costs ~40%/chunk).
//  - __ldcs on streamed inputs: keeps L2 for the output slice (-0.6 us/chunk).
// Structure: (memsetAsync chunk; scatter chunk) x 4. This round: 512-thread
// blocks + exact grid (drop bounds branch) — zero-risk launch/tail trim.

static constexpr int  PB_IN_V4_LOG2     = 18;   // per-batch input elems/4 = 2^18
static constexpr int  OUT_FLAT_LOG2     = 22;   // per-batch output elems = 2^22
static constexpr int  BATCHES           = 16;
static constexpr int  BATCHES_PER_CHUNK = 4;
static constexpr int  NCHUNKS           = BATCHES / BATCHES_PER_CHUNK;   // 4

static constexpr int  CHUNK_IN_V4    = BATCHES_PER_CHUNK << PB_IN_V4_LOG2;        // 1,048,576
static constexpr long CHUNK_OUT_ELEM = (long)BATCHES_PER_CHUNK << OUT_FLAT_LOG2;  // 16,777,216

static constexpr int  THREADS = 512;
static constexpr int  BLOCKS  = CHUNK_IN_V4 / THREADS;   // 2048 (exact)

// No-return global f32 reduction (REDG path, confirmed equivalent to
// atomicAdd-with-unused-return in R13; kept explicit for clarity).
__device__ __forceinline__ void red_add_f32(float* addr, float val) {
    asm volatile("red.global.add.f32 [%0], %1;" :: "l"(addr), "f"(val) : "memory");
}

// ---------------------------------------------------------------------------
// Scatter-add for one chunk of 4 batches.
// Each thread: 1x float4 + 1x int4 evict-first loads (front-batched -> MLP),
// then 4 divergent REDG atomics into the L2-resident 64 MB output slice.
// ---------------------------------------------------------------------------
__global__ void __launch_bounds__(THREADS)
unpool_scatter_chunk(const float4* __restrict__ pool4,
                     const int4*   __restrict__ ind4,
                     float*        __restrict__ out) {
    int t = blockIdx.x * blockDim.x + threadIdx.x;   // exact grid, no bounds check

    float4 p = __ldcs(pool4 + t);
    int4   i = __ldcs(ind4 + t);

    long base = (long)(t >> PB_IN_V4_LOG2) << OUT_FLAT_LOG2;

    red_add_f32(out + base + (long)(unsigned)i.x, p.x);
    red_add_f32(out + base + (long)(unsigned)i.y, p.y);
    red_add_f32(out + base + (long)(unsigned)i.z, p.z);
    red_add_f32(out + base + (long)(unsigned)i.w, p.w);
}

// ---------------------------------------------------------------------------
extern "C" void kernel_launch(void* const* d_in, const int* in_sizes, int n_in,
                              void* d_out, int out_size) {
    const float4* pool4 = (const float4*)d_in[0];
    const int4*   ind4  = (const int4*)d_in[1];
    float*        out   = (float*)d_out;

    for (int c = 0; c < NCHUNKS; ++c) {
        float* out_chunk = out + (long)c * CHUNK_OUT_ELEM;

        // Zero this chunk's output slice (driver zero-fill fast path;
        // lines stay L2-resident for the scatter).
        cudaMemsetAsync(out_chunk, 0, CHUNK_OUT_ELEM * sizeof(float), 0);

        // Scatter-add this chunk's 4 batches while the slice is hot in L2.
        unpool_scatter_chunk<<<BLOCKS, THREADS>>>(
            pool4 + (long)c * CHUNK_IN_V4,
            ind4  + (long)c * CHUNK_IN_V4,
            out_chunk);
    }
}

// round 15
// speedup vs baseline: 1.0073x; 1.0073x over previous
#include <cuda_runtime.h>
#include <cstdint>

// MaxUnpooling2D — per-batch flat scatter-add.
//   pool: f32  [16, 128, 128, 64]  -> 16,777,216 elements
//   ind : i32  same shape, values in [0, 4,194,304)
//   out : f32  [16, 256, 256, 64]  -> 67,108,864 elements (256 MB)
//
// FINAL (R3-R14 converged). Verified model:
//  - Wall = divergent f32 reduction service: ~2.1 cyc/atomic/SM, i.e. ~64 B
//    LTS sector-RMW per atomic -> ~1.45 GB L2 traffic ~= 129 us chip floor.
//    Measured scatter 133.6 us; invariant to ILP, occupancy, block size,
//    persistence, fused/TMA/graph-fork overlap, RED vs atomicAdd.
//  - Zeroing: driver cudaMemsetAsync zero-fill (~11 us/256 MB) beats every
//    kernel-issued store path (those pay the same LTS bytes as the atomics,
//    so overlap is conserved); cross-stream graph edges cost ~4 us each.
//  - Chunk 4 batches (64 MB out-slice) so the slice stays L2-resident
//    (126 MB L2) during its scatter; eviction costs ~40%/chunk (R7).
//  - __ldcs on streamed inputs keeps L2 for the output slice.
// Best measured: 143.6 us (~93% of LTS floor; naive baseline 206.8 us).

static constexpr int  PB_IN_V4_LOG2     = 18;   // per-batch input elems/4 = 2^18
static constexpr int  OUT_FLAT_LOG2     = 22;   // per-batch output elems = 2^22
static constexpr int  BATCHES           = 16;
static constexpr int  BATCHES_PER_CHUNK = 4;
static constexpr int  NCHUNKS           = BATCHES / BATCHES_PER_CHUNK;   // 4

static constexpr int  CHUNK_IN_V4    = BATCHES_PER_CHUNK << PB_IN_V4_LOG2;        // 1,048,576
static constexpr long CHUNK_OUT_ELEM = (long)BATCHES_PER_CHUNK << OUT_FLAT_LOG2;  // 16,777,216

static constexpr int  THREADS = 256;

// No-return global f32 reduction (REDG path).
__device__ __forceinline__ void red_add_f32(float* addr, float val) {
    asm volatile("red.global.add.f32 [%0], %1;" :: "l"(addr), "f"(val) : "memory");
}

// ---------------------------------------------------------------------------
// Scatter-add for one chunk of 4 batches.
// Each thread: 1x float4 + 1x int4 evict-first loads (front-batched -> MLP),
// then 4 divergent REDG atomics into the L2-resident 64 MB output slice.
// ---------------------------------------------------------------------------
__global__ void __launch_bounds__(THREADS)
unpool_scatter_chunk(const float4* __restrict__ pool4,
                     const int4*   __restrict__ ind4,
                     float*        __restrict__ out,
                     int n4) {
    int t = blockIdx.x * blockDim.x + threadIdx.x;
    if (t >= n4) return;

    // Front-batch loads (independent -> MLP), evict-first policy so the
    // streamed 32 MB of inputs doesn't displace the L2-resident out slice.
    float4 p = __ldcs(pool4 + t);
    int4   i = __ldcs(ind4 + t);

    int  b    = t >> PB_IN_V4_LOG2;          // batch within chunk (0..3)
    long base = (long)b << OUT_FLAT_LOG2;    // local batch output base

    red_add_f32(out + base + (long)(unsigned)i.x, p.x);
    red_add_f32(out + base + (long)(unsigned)i.y, p.y);
    red_add_f32(out + base + (long)(unsigned)i.z, p.z);
    red_add_f32(out + base + (long)(unsigned)i.w, p.w);
}

// ---------------------------------------------------------------------------
extern "C" void kernel_launch(void* const* d_in, const int* in_sizes, int n_in,
                              void* d_out, int out_size) {
    const float4* pool4 = (const float4*)d_in[0];
    const int4*   ind4  = (const int4*)d_in[1];
    float*        out   = (float*)d_out;

    const int blocks = (CHUNK_IN_V4 + THREADS - 1) / THREADS;

    for (int c = 0; c < NCHUNKS; ++c) {
        float* out_chunk = out + (long)c * CHUNK_OUT_ELEM;

        // Zero this chunk's output slice (driver zero-fill fast path;
        // lines stay L2-resident for the scatter).
        cudaMemsetAsync(out_chunk, 0, CHUNK_OUT_ELEM * sizeof(float), 0);

        // Scatter-add this chunk's 4 batches while the slice is hot in L2.
        unpool_scatter_chunk<<<blocks, THREADS>>>(
            pool4 + (long)c * CHUNK_IN_V4,
            ind4  + (long)c * CHUNK_IN_V4,
            out_chunk,
            CHUNK_IN_V4);
    }
}